// round 13
// baseline (speedup 1.0000x reference)
#include <cuda_runtime.h>
#include <cstdint>

#define B_    64
#define S_    2048
#define H_    1024
#define SPLIT 16
#define CHUNK (S_ / SPLIT)      // 128 timesteps per CTA
#define TILE  4
#define NTILES (CHUNK / TILE)   // 32
#define THREADS 256             // one float4 column slice per thread
#define WARPS (THREADS / 32)

// Scratch (allocation-free: __device__ globals)
__device__ float g_expE [B_ * S_];             // exp(tanh(score)) per (b,s)
__device__ float g_partL[B_ * SPLIT];          // partial sum of exp per chunk
__device__ float g_partC[B_ * SPLIT * H_];     // partial context per chunk (4 MiB)
__device__ int   g_count[B_];                  // arrival counter per batch

// ---------------------------------------------------------------------------
// Fused kernel, software-pipelined (R10 base + cache-policy hints):
//  - x loads use __ldcs (evict-first streaming: x is single-use, consumed
//    from registers twice within the tile, never re-read from memory)
//  - partC/partL/expE scratch uses __stcg/__ldcg (L2-only; producer CTA !=
//    consumer CTA so L1 allocation is pure overhead)
//  - outputs via __stcs (never re-read)
// Thread t owns H columns [4t,4t+4). TILE=4 with register double-buffering:
// tile k+1's loads issue BEFORE tile k's reduce/barrier, keeping DRAM busy
// through the barrier bubble. tanh in [-1,1] -> softmax needs no max.
// Epilogue: threadfence-reduction; 16th CTA per batch finishes context +
// weights (deterministic, graph-replayable; counter reset by finisher).
// ---------------------------------------------------------------------------
__global__ __launch_bounds__(THREADS, 4)
void fused_kernel(const float* __restrict__ x,
                  const float* __restrict__ w,
                  const float* __restrict__ bptr,
                  float* __restrict__ ctx_out,
                  float* __restrict__ wts_out)
{
    __shared__ float red[2][WARPS * TILE];   // ping-pong per-warp dot partials
    __shared__ float lred[TILE];
    __shared__ int   s_last;
    __shared__ float s_inv;

    const int b     = blockIdx.x / SPLIT;
    const int chunk = blockIdx.x % SPLIT;
    const int tid   = threadIdx.x;
    const int warp  = tid >> 5;
    const int lane  = tid & 31;
    const float bias = __ldg(bptr);
    const float4 w4 = reinterpret_cast<const float4*>(w)[tid];

    float4 acc = make_float4(0.f, 0.f, 0.f, 0.f);
    float lsum = 0.f;                        // warp 0, lanes 0-3 accumulate

    const int s0 = chunk * CHUNK;
    const float4* xp0 = reinterpret_cast<const float4*>(x) +
                        ((size_t)b * S_ + s0) * (H_ / 4) + tid;

    float4 xa[TILE], xb[TILE];

    // preload tile 0 into xa (streaming)
    #pragma unroll
    for (int s = 0; s < TILE; s++)
        xa[s] = __ldcs(&xp0[(size_t)s * (H_ / 4)]);

    // one pipelined tile step: consume cur[], prefetch tile nt into nxt[]
    auto step = [&](int tile, float4* cur, float4* nxt) {
        const int p = tile & 1;

        // prefetch next tile (clamped: last tile re-loads itself, in-bounds)
        const int nt = (tile + 1 < NTILES) ? tile + 1 : NTILES - 1;
        const float4* xpn = xp0 + (size_t)nt * TILE * (H_ / 4);
        #pragma unroll
        for (int s = 0; s < TILE; s++)
            nxt[s] = __ldcs(&xpn[(size_t)s * (H_ / 4)]);

        // dots from current buffer
        float d[TILE];
        #pragma unroll
        for (int s = 0; s < TILE; s++)
            d[s] = cur[s].x * w4.x + cur[s].y * w4.y
                 + cur[s].z * w4.z + cur[s].w * w4.w;

        // full warp reduce (lane 0 holds result)
        #pragma unroll
        for (int s = 0; s < TILE; s++) {
            #pragma unroll
            for (int off = 16; off; off >>= 1)
                d[s] += __shfl_xor_sync(0xffffffffu, d[s], off);
        }

        if (lane == 0) {
            #pragma unroll
            for (int s = 0; s < TILE; s++)
                red[p][warp * TILE + s] = d[s];
        }
        __syncthreads();                      // single barrier per tile

        // redundant finish in every warp: lanes 0-3 own one timestep each
        float t = 0.f;
        if (lane < TILE) {
            float v = 0.f;
            #pragma unroll
            for (int j = 0; j < WARPS; j++)
                v += red[p][j * TILE + lane];
            t = __expf(tanhf(v + bias));
            if (warp == 0) {
                __stcg(&g_expE[(size_t)b * S_ + s0 + tile * TILE + lane], t);
                lsum += t;
            }
        }

        // broadcast t and accumulate from the current register buffer
        #pragma unroll
        for (int s = 0; s < TILE; s++) {
            const float ts = __shfl_sync(0xffffffffu, t, s);
            acc.x += ts * cur[s].x;
            acc.y += ts * cur[s].y;
            acc.z += ts * cur[s].z;
            acc.w += ts * cur[s].w;
        }
    };

    #pragma unroll 1
    for (int t2 = 0; t2 < NTILES; t2 += 2) {
        step(t2,     xa, xb);
        step(t2 + 1, xb, xa);
    }

    // flush partial context (L2-only: consumer is a different CTA)
    __stcg(&reinterpret_cast<float4*>(
               g_partC + ((size_t)b * SPLIT + chunk) * H_)[tid], acc);

    // combine warp-0 lane lsums -> partL
    if (warp == 0 && lane < TILE) lred[lane] = lsum;
    __syncthreads();
    if (tid == 0) {
        float l = 0.f;
        #pragma unroll
        for (int i = 0; i < TILE; i++) l += lred[i];
        __stcg(&g_partL[b * SPLIT + chunk], l);
    }

    // -------- finisher election (threadfence reduction pattern) --------
    __threadfence();
    __syncthreads();
    if (tid == 0) {
        const int old = atomicAdd(&g_count[b], 1);
        s_last = (old == SPLIT - 1);
        if (s_last) g_count[b] = 0;   // reset for next replay (all arrived)
    }
    __syncthreads();
    if (!s_last) return;
    __threadfence();                  // acquire: see peers' flushes

    // -------- epilogue: this CTA finishes batch b --------
    if (tid < 32) {
        float l = (tid < SPLIT) ? __ldcg(&g_partL[b * SPLIT + tid]) : 0.f;
        #pragma unroll
        for (int off = 16; off; off >>= 1)
            l += __shfl_xor_sync(0xffffffffu, l, off);
        if (tid == 0) s_inv = 1.f / l;
    }
    __syncthreads();
    const float inv = s_inv;

    // context[b][:] : 256 threads x one float4, 16 independent partial loads
    float4 c = make_float4(0.f, 0.f, 0.f, 0.f);
    #pragma unroll
    for (int cc = 0; cc < SPLIT; cc++) {
        float4 v = __ldcg(&reinterpret_cast<const float4*>(
            g_partC + ((size_t)b * SPLIT + cc) * H_)[tid]);
        c.x += v.x; c.y += v.y; c.z += v.z; c.w += v.w;
    }
    c.x *= inv; c.y *= inv; c.z *= inv; c.w *= inv;
    __stcs(&reinterpret_cast<float4*>(ctx_out)[b * (H_ / 4) + tid], c);

    // weights[b][:] : S/4 = 512 float4, 2 per thread
    #pragma unroll
    for (int i = 0; i < S_ / 4 / THREADS; i++) {
        const int idx = b * (S_ / 4) + i * THREADS + tid;
        float4 e = __ldcg(&reinterpret_cast<const float4*>(g_expE)[idx]);
        e.x *= inv; e.y *= inv; e.z *= inv; e.w *= inv;
        __stcs(&reinterpret_cast<float4*>(wts_out)[idx], e);
    }
}

extern "C" void kernel_launch(void* const* d_in, const int* in_sizes, int n_in,
                              void* d_out, int out_size)
{
    const float* x    = (const float*)d_in[0];   // rnn_output [B,S,H]
    const float* w    = (const float*)d_in[1];   // attn_w [H]
    const float* bptr = (const float*)d_in[2];   // attn_b scalar

    float* out = (float*)d_out;                  // context [B,H] then weights [B,S]
    float* ctx_out = out;
    float* wts_out = out + (size_t)B_ * H_;

    fused_kernel<<<B_ * SPLIT, THREADS>>>(x, w, bptr, ctx_out, wts_out);
}

// round 14
// speedup vs baseline: 1.0069x; 1.0069x over previous
#include <cuda_runtime.h>
#include <cstdint>

#define B_    64
#define S_    2048
#define H_    1024
#define SPLIT 16
#define CHUNK (S_ / SPLIT)      // 128 timesteps per CTA
#define TILE  4
#define NTILES (CHUNK / TILE)   // 32
#define THREADS 256             // one float4 column slice per thread
#define WARPS (THREADS / 32)

// Scratch (allocation-free: __device__ globals)
__device__ float g_expE [B_ * S_];             // exp(tanh(score)) per (b,s)
__device__ float g_partL[B_ * SPLIT];          // partial sum of exp per chunk
__device__ float g_partC[B_ * SPLIT * H_];     // partial context per chunk (4 MiB)
__device__ int   g_count[B_];                  // arrival counter per batch

__device__ __forceinline__ float tanh_approx(float v) {
    float r;
    asm("tanh.approx.f32 %0, %1;" : "=f"(r) : "f"(v));
    return r;
}

// ---------------------------------------------------------------------------
// Fused kernel, software-pipelined (R13 base + shorter per-tile critical path)
//  - interleaved 4-row warp reduction: 9 SHFL instead of 20, result lands
//    lane L = full warp sum of row (L&3); lanes 0-3 publish one STS each.
//  - tanh.approx.f32 (1 op vs ~20-instr polynomial; err ~1e-5 << 1e-3 budget)
//  - x loads via __ldcs (single-use streaming), scratch via __stcg/__ldcg,
//    outputs via __stcs.
// Thread t owns H columns [4t,4t+4). TILE=4 register double-buffering: tile
// k+1's loads issue BEFORE tile k's reduce/barrier. tanh in [-1,1] -> softmax
// needs no max subtraction.
// Epilogue: threadfence-reduction; 16th CTA per batch finishes context +
// weights (deterministic, graph-replayable; counter reset by finisher).
// ---------------------------------------------------------------------------
__global__ __launch_bounds__(THREADS, 4)
void fused_kernel(const float* __restrict__ x,
                  const float* __restrict__ w,
                  const float* __restrict__ bptr,
                  float* __restrict__ ctx_out,
                  float* __restrict__ wts_out)
{
    __shared__ float red[2][WARPS * TILE];   // ping-pong per-warp dot partials
    __shared__ float lred[TILE];
    __shared__ int   s_last;
    __shared__ float s_inv;

    const int b     = blockIdx.x / SPLIT;
    const int chunk = blockIdx.x % SPLIT;
    const int tid   = threadIdx.x;
    const int warp  = tid >> 5;
    const int lane  = tid & 31;
    const float bias = __ldg(bptr);
    const float4 w4 = reinterpret_cast<const float4*>(w)[tid];

    float4 acc = make_float4(0.f, 0.f, 0.f, 0.f);
    float lsum = 0.f;                        // warp 0, lanes 0-3 accumulate

    const int s0 = chunk * CHUNK;
    const float4* xp0 = reinterpret_cast<const float4*>(x) +
                        ((size_t)b * S_ + s0) * (H_ / 4) + tid;

    float4 xa[TILE], xb[TILE];

    // preload tile 0 into xa (streaming)
    #pragma unroll
    for (int s = 0; s < TILE; s++)
        xa[s] = __ldcs(&xp0[(size_t)s * (H_ / 4)]);

    // one pipelined tile step: consume cur[], prefetch tile nt into nxt[]
    auto step = [&](int tile, float4* cur, float4* nxt) {
        const int p = tile & 1;

        // prefetch next tile (clamped: last tile re-loads itself, in-bounds)
        const int nt = (tile + 1 < NTILES) ? tile + 1 : NTILES - 1;
        const float4* xpn = xp0 + (size_t)nt * TILE * (H_ / 4);
        #pragma unroll
        for (int s = 0; s < TILE; s++)
            nxt[s] = __ldcs(&xpn[(size_t)s * (H_ / 4)]);

        // dots from current buffer
        float d[TILE];
        #pragma unroll
        for (int s = 0; s < TILE; s++)
            d[s] = cur[s].x * w4.x + cur[s].y * w4.y
                 + cur[s].z * w4.z + cur[s].w * w4.w;

        // interleaved 4-row warp reduce: 9 SHFL total.
        // Stage 1 (xor 1): every lane holds pair-sum of each row.
        #pragma unroll
        for (int s = 0; s < TILE; s++)
            d[s] += __shfl_xor_sync(0xffffffffu, d[s], 1);
        // select by bit0 -> 2 live values (row parity tracked by lane bit0)
        float e0 = (lane & 1) ? d[1] : d[0];
        float e1 = (lane & 1) ? d[3] : d[2];
        e0 += __shfl_xor_sync(0xffffffffu, e0, 2);
        e1 += __shfl_xor_sync(0xffffffffu, e1, 2);
        // select by bit1 -> 1 live value; lane L now carries row (L & 3)
        float f = (lane & 2) ? e1 : e0;
        f += __shfl_xor_sync(0xffffffffu, f, 4);
        f += __shfl_xor_sync(0xffffffffu, f, 8);
        f += __shfl_xor_sync(0xffffffffu, f, 16);
        // lane L (< 4) holds the full warp sum of row (L & 3)
        if (lane < TILE)
            red[p][warp * TILE + lane] = f;

        __syncthreads();                      // single barrier per tile

        // redundant finish in every warp: lanes 0-3 own one timestep each
        float t = 0.f;
        if (lane < TILE) {
            float v = 0.f;
            #pragma unroll
            for (int j = 0; j < WARPS; j++)
                v += red[p][j * TILE + lane];
            t = __expf(tanh_approx(v + bias));
            if (warp == 0) {
                __stcg(&g_expE[(size_t)b * S_ + s0 + tile * TILE + lane], t);
                lsum += t;
            }
        }

        // broadcast t and accumulate from the current register buffer
        #pragma unroll
        for (int s = 0; s < TILE; s++) {
            const float ts = __shfl_sync(0xffffffffu, t, s);
            acc.x += ts * cur[s].x;
            acc.y += ts * cur[s].y;
            acc.z += ts * cur[s].z;
            acc.w += ts * cur[s].w;
        }
    };

    #pragma unroll 1
    for (int t2 = 0; t2 < NTILES; t2 += 2) {
        step(t2,     xa, xb);
        step(t2 + 1, xb, xa);
    }

    // flush partial context (L2-only: consumer is a different CTA)
    __stcg(&reinterpret_cast<float4*>(
               g_partC + ((size_t)b * SPLIT + chunk) * H_)[tid], acc);

    // combine warp-0 lane lsums -> partL
    if (warp == 0 && lane < TILE) lred[lane] = lsum;
    __syncthreads();
    if (tid == 0) {
        float l = 0.f;
        #pragma unroll
        for (int i = 0; i < TILE; i++) l += lred[i];
        __stcg(&g_partL[b * SPLIT + chunk], l);
    }

    // -------- finisher election (threadfence reduction pattern) --------
    __threadfence();
    __syncthreads();
    if (tid == 0) {
        const int old = atomicAdd(&g_count[b], 1);
        s_last = (old == SPLIT - 1);
        if (s_last) g_count[b] = 0;   // reset for next replay (all arrived)
    }
    __syncthreads();
    if (!s_last) return;
    __threadfence();                  // acquire: see peers' flushes

    // -------- epilogue: this CTA finishes batch b --------
    if (tid < 32) {
        float l = (tid < SPLIT) ? __ldcg(&g_partL[b * SPLIT + tid]) : 0.f;
        #pragma unroll
        for (int off = 16; off; off >>= 1)
            l += __shfl_xor_sync(0xffffffffu, l, off);
        if (tid == 0) s_inv = 1.f / l;
    }
    __syncthreads();
    const float inv = s_inv;

    // context[b][:] : 256 threads x one float4, 16 independent partial loads
    float4 c = make_float4(0.f, 0.f, 0.f, 0.f);
    #pragma unroll
    for (int cc = 0; cc < SPLIT; cc++) {
        float4 v = __ldcg(&reinterpret_cast<const float4*>(
            g_partC + ((size_t)b * SPLIT + cc) * H_)[tid]);
        c.x += v.x; c.y += v.y; c.z += v.z; c.w += v.w;
    }
    c.x *= inv; c.y *= inv; c.z *= inv; c.w *= inv;
    __stcs(&reinterpret_cast<float4*>(ctx_out)[b * (H_ / 4) + tid], c);

    // weights[b][:] : S/4 = 512 float4, 2 per thread
    #pragma unroll
    for (int i = 0; i < S_ / 4 / THREADS; i++) {
        const int idx = b * (S_ / 4) + i * THREADS + tid;
        float4 e = __ldcg(&reinterpret_cast<const float4*>(g_expE)[idx]);
        e.x *= inv; e.y *= inv; e.z *= inv; e.w *= inv;
        __stcs(&reinterpret_cast<float4*>(wts_out)[idx], e);
    }
}

extern "C" void kernel_launch(void* const* d_in, const int* in_sizes, int n_in,
                              void* d_out, int out_size)
{
    const float* x    = (const float*)d_in[0];   // rnn_output [B,S,H]
    const float* w    = (const float*)d_in[1];   // attn_w [H]
    const float* bptr = (const float*)d_in[2];   // attn_b scalar

    float* out = (float*)d_out;                  // context [B,H] then weights [B,S]
    float* ctx_out = out;
    float* wts_out = out + (size_t)B_ * H_;

    fused_kernel<<<B_ * SPLIT, THREADS>>>(x, w, bptr, ctx_out, wts_out);
}